// round 1
// baseline (speedup 1.0000x reference)
#include <cuda_runtime.h>
#include <math.h>

// Problem constants (shapes are fixed by the dataset)
#define NB 2
#define NN 8192
#define NF 512
#define NHD 512   // H*D
#define NH 8
#define ND 64

// -------- scratch (device globals; no allocation allowed) --------
__device__ float g_h[NB * NN * NHD];        // 32 MB: h = x @ W.T
__device__ float g_s1[NB * NN * NH];
__device__ float g_s2[NB * NN * NH];
__device__ float g_w[NB * NN * NH];
__device__ int   g_last[NN];
__device__ int   g_cnt[NN];
__device__ int   g_cur[NN];
__device__ int   g_off[NN + 1];
__device__ int   g_csr[131072];             // room for E up to 128K (E=65536)

// -------- init --------
__global__ void init_kernel(int N)
{
    int i = blockIdx.x * blockDim.x + threadIdx.x;
    if (i < N) { g_last[i] = -1; g_cnt[i] = 0; g_cur[i] = 0; }
}

// -------- SGEMM: C[m][n] = sum_k A[m][k] * B[n][k]  (A=x 16384x512, B=W 512x512, C=g_h) --------
__global__ __launch_bounds__(256) void sgemm_kernel(
    const float* __restrict__ A, const float* __restrict__ B,
    int M, int N, int K)
{
    __shared__ float As[8][132];
    __shared__ float Bs[8][132];
    const int tid = threadIdx.x;
    const int tx = tid & 15, ty = tid >> 4;
    const int m0 = blockIdx.y * 128, n0 = blockIdx.x * 128;
    const int lrow = tid >> 1, lc = (tid & 1) * 4;
    const float* Aptr = A + (size_t)(m0 + lrow) * K + lc;
    const float* Bptr = B + (size_t)(n0 + lrow) * K + lc;

    float acc[8][8];
    #pragma unroll
    for (int i = 0; i < 8; i++)
        #pragma unroll
        for (int j = 0; j < 8; j++) acc[i][j] = 0.f;

    for (int k0 = 0; k0 < K; k0 += 8) {
        float4 av = *(const float4*)(Aptr + k0);
        float4 bv = *(const float4*)(Bptr + k0);
        As[lc + 0][lrow] = av.x; As[lc + 1][lrow] = av.y;
        As[lc + 2][lrow] = av.z; As[lc + 3][lrow] = av.w;
        Bs[lc + 0][lrow] = bv.x; Bs[lc + 1][lrow] = bv.y;
        Bs[lc + 2][lrow] = bv.z; Bs[lc + 3][lrow] = bv.w;
        __syncthreads();
        #pragma unroll
        for (int kk = 0; kk < 8; kk++) {
            float ar[8], br[8];
            *(float4*)(ar)     = *(const float4*)&As[kk][ty * 8];
            *(float4*)(ar + 4) = *(const float4*)&As[kk][ty * 8 + 4];
            *(float4*)(br)     = *(const float4*)&Bs[kk][tx * 8];
            *(float4*)(br + 4) = *(const float4*)&Bs[kk][tx * 8 + 4];
            #pragma unroll
            for (int i = 0; i < 8; i++)
                #pragma unroll
                for (int j = 0; j < 8; j++)
                    acc[i][j] += ar[i] * br[j];
        }
        __syncthreads();
    }

    #pragma unroll
    for (int i = 0; i < 8; i++) {
        float* crow = g_h + (size_t)(m0 + ty * 8 + i) * N + n0 + tx * 8;
        *(float4*)(crow)     = make_float4(acc[i][0], acc[i][1], acc[i][2], acc[i][3]);
        *(float4*)(crow + 4) = make_float4(acc[i][4], acc[i][5], acc[i][6], acc[i][7]);
    }
}

// -------- per-node scores s1 = h.a1, s2 = h.a2  (one warp per (b,n)) --------
__global__ void score_kernel(const float* __restrict__ a, int BN)
{
    int warp = (blockIdx.x * blockDim.x + threadIdx.x) >> 5;
    int lane = threadIdx.x & 31;
    if (warp >= BN) return;
    const float* hrow = g_h + (size_t)warp * NHD + lane * 16;
    int head  = lane >> 2;
    int dbase = (lane & 3) * 16;
    float p1 = 0.f, p2 = 0.f;
    #pragma unroll
    for (int i = 0; i < 16; i++) {
        float v = hrow[i];
        p1 += v * a[dbase + i];
        p2 += v * a[64 + dbase + i];
    }
    p1 += __shfl_xor_sync(0xffffffffu, p1, 1);
    p2 += __shfl_xor_sync(0xffffffffu, p2, 1);
    p1 += __shfl_xor_sync(0xffffffffu, p1, 2);
    p2 += __shfl_xor_sync(0xffffffffu, p2, 2);
    if ((lane & 3) == 0) {
        g_s1[(size_t)warp * NH + head] = p1;
        g_s2[(size_t)warp * NH + head] = p2;
    }
}

// -------- edge pass 1: last_edge (atomicMax) + degree counts --------
__global__ void edge1_kernel(const int* __restrict__ ei, int E)
{
    int e = blockIdx.x * blockDim.x + threadIdx.x;
    if (e >= E) return;
    int s = ei[e];
    atomicMax(&g_last[s], e);
    atomicAdd(&g_cnt[s], 1);
}

// -------- exclusive scan over counts (single block, 1024 threads x 8) --------
__global__ void scan_kernel()
{
    __shared__ int sums[1024];
    int tid = threadIdx.x;
    int base = tid * 8;
    int local[8];
    int s = 0;
    #pragma unroll
    for (int i = 0; i < 8; i++) { local[i] = s; s += g_cnt[base + i]; }
    sums[tid] = s;
    __syncthreads();
    for (int off = 1; off < 1024; off <<= 1) {
        int v = 0;
        if (tid >= off) v = sums[tid - off];
        __syncthreads();
        sums[tid] += v;
        __syncthreads();
    }
    int prev = (tid == 0) ? 0 : sums[tid - 1];
    #pragma unroll
    for (int i = 0; i < 8; i++) g_off[base + i] = prev + local[i];
    if (tid == 1023) g_off[NN] = sums[1023];
}

// -------- edge pass 2: fill CSR with dst values --------
__global__ void edge2_kernel(const int* __restrict__ ei, int E)
{
    int e = blockIdx.x * blockDim.x + threadIdx.x;
    if (e >= E) return;
    int s = ei[e];
    int p = atomicAdd(&g_cur[s], 1);
    g_csr[g_off[s] + p] = ei[E + e];
}

// -------- attention weights: softmax over B=2 at last_edge only --------
__global__ void w_kernel(const int* __restrict__ ei, int N, int E)
{
    int idx = blockIdx.x * blockDim.x + threadIdx.x;
    if (idx >= N * NH) return;
    int n = idx >> 3, h = idx & 7;
    int le = g_last[n];
    float w0 = 0.f, w1 = 0.f;
    if (le >= 0) {
        int dle = ei[E + le];
        float sc0 = g_s1[((size_t)0 * N + n) * NH + h] + g_s2[((size_t)0 * N + dle) * NH + h];
        float sc1 = g_s1[((size_t)1 * N + n) * NH + h] + g_s2[((size_t)1 * N + dle) * NH + h];
        sc0 = sc0 > 0.f ? sc0 : 0.2f * sc0;
        sc1 = sc1 > 0.f ? sc1 : 0.2f * sc1;
        float m  = fmaxf(sc0, sc1);
        float e0 = expf(sc0 - m), e1 = expf(sc1 - m);
        float inv = 1.f / (e0 + e1);
        w0 = e0 * inv; w1 = e1 * inv;
    }
    g_w[((size_t)0 * N + n) * NH + h] = w0;
    g_w[((size_t)1 * N + n) * NH + h] = w1;
}

// -------- aggregation: gather CSR neighbors, head-weight, mean over heads --------
__global__ __launch_bounds__(128) void agg_kernel(float* __restrict__ out, int N)
{
    int bn = blockIdx.x;          // b*N + n
    int n  = bn & (N - 1);        // N = 8192 (pow2)
    int b  = bn >> 13;
    int tid = threadIdx.x;
    __shared__ float s[NHD];

    int beg = g_off[n], end = g_off[n + 1];
    const float* hbase = g_h + (size_t)b * N * NHD;
    float4 acc = make_float4(0.f, 0.f, 0.f, 0.f);
    for (int j = beg; j < end; j++) {
        int d = g_csr[j];
        const float4* row = (const float4*)(hbase + (size_t)d * NHD);
        float4 v = row[tid];
        acc.x += v.x; acc.y += v.y; acc.z += v.z; acc.w += v.w;
    }
    ((float4*)s)[tid] = acc;
    __syncthreads();
    if (tid < ND) {
        const float* wrow = g_w + (size_t)bn * NH;
        float o = 0.f;
        #pragma unroll
        for (int h = 0; h < NH; h++) o += wrow[h] * s[h * ND + tid];
        out[(size_t)bn * ND + tid] = o * 0.125f;
    }
}

extern "C" void kernel_launch(void* const* d_in, const int* in_sizes, int n_in,
                              void* d_out, int out_size)
{
    const float* x  = (const float*)d_in[0];
    const int*   ei = (const int*)d_in[1];
    const float* W  = (const float*)d_in[2];
    const float* a  = (const float*)d_in[3];
    float* out = (float*)d_out;

    const int N = NN;
    const int E = in_sizes[1] / 2;
    const int M = NB * NN;          // 16384

    init_kernel<<<(N + 255) / 256, 256>>>(N);
    sgemm_kernel<<<dim3(NHD / 128, M / 128), 256>>>(x, W, M, NHD, NF);
    score_kernel<<<(M * 32 + 255) / 256, 256>>>(a, M);
    edge1_kernel<<<(E + 255) / 256, 256>>>(ei, E);
    scan_kernel<<<1, 1024>>>();
    edge2_kernel<<<(E + 255) / 256, 256>>>(ei, E);
    w_kernel<<<(N * NH + 255) / 256, 256>>>(ei, N, E);
    agg_kernel<<<NB * NN, 128>>>(out, N);
}

// round 3
// speedup vs baseline: 1.3786x; 1.3786x over previous
#include <cuda_runtime.h>
#include <cuda_bf16.h>
#include <math.h>
#include <stdint.h>

// Problem constants (fixed by the dataset)
#define NB 2
#define NN 8192
#define NF 512
#define NHD 512   // H*D
#define NH 8
#define ND 64

// -------- scratch (device globals; no allocation allowed) --------
__device__ float g_h[NB * NN * NHD];        // 32 MB: h = x @ W.T
__device__ float g_s1[NB * NN * NH];
__device__ float g_s2[NB * NN * NH];
__device__ float g_w[NB * NN * NH];
__device__ int   g_last[NN];
__device__ int   g_cnt[NN];
__device__ int   g_cur[NN];
__device__ int   g_off[NN + 1];
__device__ int   g_csr[131072];

// ======================= helpers =======================
__device__ __forceinline__ uint32_t smem_u32(const void* p) {
    uint32_t a;
    asm("{ .reg .u64 t; cvta.to.shared.u64 t, %1; cvt.u32.u64 %0, t; }" : "=r"(a) : "l"(p));
    return a;
}
__device__ __forceinline__ void ldsm_x4(uint32_t* r, uint32_t addr) {
    asm volatile("ldmatrix.sync.aligned.m8n8.x4.shared.b16 {%0,%1,%2,%3}, [%4];"
        : "=r"(r[0]), "=r"(r[1]), "=r"(r[2]), "=r"(r[3]) : "r"(addr));
}
__device__ __forceinline__ void mma_bf16(float* d, const uint32_t* a, const uint32_t* b) {
    asm volatile("mma.sync.aligned.m16n8k16.row.col.f32.bf16.bf16.f32 "
        "{%0,%1,%2,%3}, {%4,%5,%6,%7}, {%8,%9}, {%0,%1,%2,%3};"
        : "+f"(d[0]), "+f"(d[1]), "+f"(d[2]), "+f"(d[3])
        : "r"(a[0]), "r"(a[1]), "r"(a[2]), "r"(a[3]), "r"(b[0]), "r"(b[1]));
}
__device__ __forceinline__ uint32_t pack2(__nv_bfloat16 x, __nv_bfloat16 y) {
    uint32_t lo = __bfloat16_as_ushort(x), hi = __bfloat16_as_ushort(y);
    return (hi << 16) | lo;
}

// ======================= bf16-split GEMM =======================
// C[m][n] = sum_k A[m][k]*B[n][k]; A = x (16384x512), B = W (512x512), C = g_h
// Block tile 128x128, BK=64, 8 warps (2x4), warp tile 64x32, mma m16n8k16.
// smem tiles (per stage): Ah, Al, Bh, Bl each 128 rows x 64 bf16 (row stride 72 bf16 = 144B)
#define ROWB 144
#define TILE_B (128 * ROWB)             // 18432
#define STAGE_B (4 * TILE_B)            // 73728
#define GEMM_SMEM (2 * STAGE_B)         // 147456

__global__ __launch_bounds__(256, 1) void gemm_split(
    const float* __restrict__ A, const float* __restrict__ Bw)
{
    extern __shared__ char smem[];
    const uint32_t sb = smem_u32(smem);
    const int tid = threadIdx.x, wid = tid >> 5, lid = tid & 31;
    const int m0 = blockIdx.y * 128, n0 = blockIdx.x * 128;
    const int warp_m = (wid >> 2) * 64, warp_n = (wid & 3) * 32;

    // fill mapping: thread t -> row t>>1, 32 floats at col (t&1)*32
    const int frow = tid >> 1, fhalf = tid & 1;
    const float* Ag = A  + (size_t)(m0 + frow) * NF + fhalf * 32;
    const float* Bg = Bw + (size_t)(n0 + frow) * NF + fhalf * 32;
    const uint32_t fbase = frow * ROWB + fhalf * 64;   // byte offset within a tile

    // ldmatrix per-lane base offsets (bytes, within a tile)
    const uint32_t a_off = (uint32_t)((warp_m + (lid & 15)) * 72 + (lid >> 4) * 8) * 2;
    const uint32_t b_off = (uint32_t)((warp_n + (lid & 7) + (lid >> 4) * 8) * 72
                                      + ((lid >> 3) & 1) * 8) * 2;

    float acc[4][4][4];
    #pragma unroll
    for (int i = 0; i < 4; i++)
        #pragma unroll
        for (int j = 0; j < 4; j++)
            #pragma unroll
            for (int v = 0; v < 4; v++) acc[i][j][v] = 0.f;

    #pragma unroll 1
    for (int kc = 0; kc < 8; kc++) {
        const uint32_t stg = (kc & 1) ? STAGE_B : 0;
        // ---- fill Ah/Al/Bh/Bl ----
        {
            const uint32_t sA = sb + stg + fbase;
            const uint32_t sB = sA + 2 * TILE_B;
            #pragma unroll
            for (int i = 0; i < 8; i++) {
                float4 v = *(const float4*)(Ag + kc * 64 + i * 4);
                __nv_bfloat16 hx = __float2bfloat16_rn(v.x), hy = __float2bfloat16_rn(v.y);
                __nv_bfloat16 hz = __float2bfloat16_rn(v.z), hw = __float2bfloat16_rn(v.w);
                uint2 hi = make_uint2(pack2(hx, hy), pack2(hz, hw));
                uint2 lo = make_uint2(
                    pack2(__float2bfloat16_rn(v.x - __bfloat162float(hx)),
                          __float2bfloat16_rn(v.y - __bfloat162float(hy))),
                    pack2(__float2bfloat16_rn(v.z - __bfloat162float(hz)),
                          __float2bfloat16_rn(v.w - __bfloat162float(hw))));
                *(uint2*)(smem + (sA - sb) + i * 8)          = hi;
                *(uint2*)(smem + (sA - sb) + TILE_B + i * 8) = lo;

                float4 w = *(const float4*)(Bg + kc * 64 + i * 4);
                hx = __float2bfloat16_rn(w.x); hy = __float2bfloat16_rn(w.y);
                hz = __float2bfloat16_rn(w.z); hw = __float2bfloat16_rn(w.w);
                hi = make_uint2(pack2(hx, hy), pack2(hz, hw));
                lo = make_uint2(
                    pack2(__float2bfloat16_rn(w.x - __bfloat162float(hx)),
                          __float2bfloat16_rn(w.y - __bfloat162float(hy))),
                    pack2(__float2bfloat16_rn(w.z - __bfloat162float(hz)),
                          __float2bfloat16_rn(w.w - __bfloat162float(hw))));
                *(uint2*)(smem + (sB - sb) + i * 8)          = hi;
                *(uint2*)(smem + (sB - sb) + TILE_B + i * 8) = lo;
            }
        }
        __syncthreads();
        // ---- compute ----
        {
            const uint32_t aHi = sb + stg + a_off;
            const uint32_t aLo = aHi + TILE_B;
            const uint32_t bHi = sb + stg + 2 * TILE_B + b_off;
            const uint32_t bLo = bHi + TILE_B;
            #pragma unroll
            for (int ks = 0; ks < 4; ks++) {
                uint32_t ah[4][4], al[4][4], bh[2][4], bl[2][4];
                #pragma unroll
                for (int mt = 0; mt < 4; mt++) {
                    ldsm_x4(ah[mt], aHi + mt * (16 * ROWB) + ks * 32);
                    ldsm_x4(al[mt], aLo + mt * (16 * ROWB) + ks * 32);
                }
                #pragma unroll
                for (int np = 0; np < 2; np++) {
                    ldsm_x4(bh[np], bHi + np * (16 * ROWB) + ks * 32);
                    ldsm_x4(bl[np], bLo + np * (16 * ROWB) + ks * 32);
                }
                #pragma unroll
                for (int mt = 0; mt < 4; mt++)
                    #pragma unroll
                    for (int nt = 0; nt < 4; nt++) {
                        const uint32_t* bhp = &bh[nt >> 1][(nt & 1) * 2];
                        const uint32_t* blp = &bl[nt >> 1][(nt & 1) * 2];
                        mma_bf16(acc[mt][nt], ah[mt], bhp);
                        mma_bf16(acc[mt][nt], ah[mt], blp);
                        mma_bf16(acc[mt][nt], al[mt], bhp);
                    }
            }
        }
    }

    // ---- epilogue: write C ----
    #pragma unroll
    for (int mt = 0; mt < 4; mt++) {
        const int row0 = m0 + warp_m + mt * 16 + (lid >> 2);
        #pragma unroll
        for (int nt = 0; nt < 4; nt++) {
            const int col = n0 + warp_n + nt * 8 + (lid & 3) * 2;
            *(float2*)(g_h + (size_t)row0 * NHD + col) =
                make_float2(acc[mt][nt][0], acc[mt][nt][1]);
            *(float2*)(g_h + (size_t)(row0 + 8) * NHD + col) =
                make_float2(acc[mt][nt][2], acc[mt][nt][3]);
        }
    }
}

// ======================= graph pipeline (unchanged, passed R1) =======================
__global__ void init_kernel(int N)
{
    int i = blockIdx.x * blockDim.x + threadIdx.x;
    if (i < N) { g_last[i] = -1; g_cnt[i] = 0; g_cur[i] = 0; }
}

__global__ void score_kernel(const float* __restrict__ a, int BN)
{
    int warp = (blockIdx.x * blockDim.x + threadIdx.x) >> 5;
    int lane = threadIdx.x & 31;
    if (warp >= BN) return;
    const float* hrow = g_h + (size_t)warp * NHD + lane * 16;
    int head  = lane >> 2;
    int dbase = (lane & 3) * 16;
    float p1 = 0.f, p2 = 0.f;
    #pragma unroll
    for (int i = 0; i < 16; i++) {
        float v = hrow[i];
        p1 += v * a[dbase + i];
        p2 += v * a[64 + dbase + i];
    }
    p1 += __shfl_xor_sync(0xffffffffu, p1, 1);
    p2 += __shfl_xor_sync(0xffffffffu, p2, 1);
    p1 += __shfl_xor_sync(0xffffffffu, p1, 2);
    p2 += __shfl_xor_sync(0xffffffffu, p2, 2);
    if ((lane & 3) == 0) {
        g_s1[(size_t)warp * NH + head] = p1;
        g_s2[(size_t)warp * NH + head] = p2;
    }
}

__global__ void edge1_kernel(const int* __restrict__ ei, int E)
{
    int e = blockIdx.x * blockDim.x + threadIdx.x;
    if (e >= E) return;
    int s = ei[e];
    atomicMax(&g_last[s], e);
    atomicAdd(&g_cnt[s], 1);
}

__global__ void scan_kernel()
{
    __shared__ int sums[1024];
    int tid = threadIdx.x;
    int base = tid * 8;
    int local[8];
    int s = 0;
    #pragma unroll
    for (int i = 0; i < 8; i++) { local[i] = s; s += g_cnt[base + i]; }
    sums[tid] = s;
    __syncthreads();
    for (int off = 1; off < 1024; off <<= 1) {
        int v = 0;
        if (tid >= off) v = sums[tid - off];
        __syncthreads();
        sums[tid] += v;
        __syncthreads();
    }
    int prev = (tid == 0) ? 0 : sums[tid - 1];
    #pragma unroll
    for (int i = 0; i < 8; i++) g_off[base + i] = prev + local[i];
    if (tid == 1023) g_off[NN] = sums[1023];
}

__global__ void edge2_kernel(const int* __restrict__ ei, int E)
{
    int e = blockIdx.x * blockDim.x + threadIdx.x;
    if (e >= E) return;
    int s = ei[e];
    int p = atomicAdd(&g_cur[s], 1);
    g_csr[g_off[s] + p] = ei[E + e];
}

__global__ void w_kernel(const int* __restrict__ ei, int N, int E)
{
    int idx = blockIdx.x * blockDim.x + threadIdx.x;
    if (idx >= N * NH) return;
    int n = idx >> 3, h = idx & 7;
    int le = g_last[n];
    float w0 = 0.f, w1 = 0.f;
    if (le >= 0) {
        int dle = ei[E + le];
        float sc0 = g_s1[((size_t)0 * N + n) * NH + h] + g_s2[((size_t)0 * N + dle) * NH + h];
        float sc1 = g_s1[((size_t)1 * N + n) * NH + h] + g_s2[((size_t)1 * N + dle) * NH + h];
        sc0 = sc0 > 0.f ? sc0 : 0.2f * sc0;
        sc1 = sc1 > 0.f ? sc1 : 0.2f * sc1;
        float m  = fmaxf(sc0, sc1);
        float e0 = expf(sc0 - m), e1 = expf(sc1 - m);
        float inv = 1.f / (e0 + e1);
        w0 = e0 * inv; w1 = e1 * inv;
    }
    g_w[((size_t)0 * N + n) * NH + h] = w0;
    g_w[((size_t)1 * N + n) * NH + h] = w1;
}

__global__ __launch_bounds__(128) void agg_kernel(float* __restrict__ out, int N)
{
    int bn = blockIdx.x;
    int n  = bn & (N - 1);
    int b  = bn >> 13;
    int tid = threadIdx.x;
    __shared__ float s[NHD];

    int beg = g_off[n], end = g_off[n + 1];
    const float* hbase = g_h + (size_t)b * N * NHD;
    float4 acc = make_float4(0.f, 0.f, 0.f, 0.f);
    for (int j = beg; j < end; j++) {
        int d = g_csr[j];
        const float4* row = (const float4*)(hbase + (size_t)d * NHD);
        float4 v = row[tid];
        acc.x += v.x; acc.y += v.y; acc.z += v.z; acc.w += v.w;
    }
    ((float4*)s)[tid] = acc;
    __syncthreads();
    if (tid < ND) {
        const float* wrow = g_w + (size_t)bn * NH;
        float o = 0.f;
        #pragma unroll
        for (int h = 0; h < NH; h++) o += wrow[h] * s[h * ND + tid];
        out[(size_t)bn * ND + tid] = o * 0.125f;
    }
}

extern "C" void kernel_launch(void* const* d_in, const int* in_sizes, int n_in,
                              void* d_out, int out_size)
{
    const float* x  = (const float*)d_in[0];
    const int*   ei = (const int*)d_in[1];
    const float* W  = (const float*)d_in[2];
    const float* a  = (const float*)d_in[3];
    float* out = (float*)d_out;

    const int N = NN;
    const int E = in_sizes[1] / 2;
    const int M = NB * NN;

    cudaFuncSetAttribute(gemm_split, cudaFuncAttributeMaxDynamicSharedMemorySize, GEMM_SMEM);

    init_kernel<<<(N + 255) / 256, 256>>>(N);
    gemm_split<<<dim3(NHD / 128, M / 128), 256, GEMM_SMEM>>>(x, W);
    score_kernel<<<(M * 32 + 255) / 256, 256>>>(a, M);
    edge1_kernel<<<(E + 255) / 256, 256>>>(ei, E);
    scan_kernel<<<1, 1024>>>();
    edge2_kernel<<<(E + 255) / 256, 256>>>(ei, E);
    w_kernel<<<(N * NH + 255) / 256, 256>>>(ei, N, E);
    agg_kernel<<<NB * NN, 128>>>(out, N);
}

// round 4
// speedup vs baseline: 1.6276x; 1.1806x over previous
#include <cuda_runtime.h>
#include <cuda_bf16.h>
#include <math.h>
#include <stdint.h>

// Problem constants (fixed by the dataset)
#define NB 2
#define NN 8192
#define NF 512
#define NHD 512   // H*D
#define NH 8
#define ND 64
#define NM (NB * NN)   // 16384

// -------- scratch (device globals; no allocation allowed) --------
__device__ float g_h[NB * NN * NHD];                 // 32 MB
__device__ __nv_bfloat16 g_xh[NM * NF];              // 16 MB
__device__ __nv_bfloat16 g_xl[NM * NF];              // 16 MB
__device__ __nv_bfloat16 g_wh[NHD * NF];             // 0.5 MB
__device__ __nv_bfloat16 g_wl[NHD * NF];             // 0.5 MB
__device__ float g_s1[NB * NN * NH];
__device__ float g_s2[NB * NN * NH];
__device__ float g_w[NB * NN * NH];
__device__ int   g_last[NN];
__device__ int   g_cnt[NN];
__device__ int   g_cur[NN];
__device__ int   g_off[NN + 1];
__device__ int   g_csr[131072];

// ======================= helpers =======================
__device__ __forceinline__ uint32_t smem_u32(const void* p) {
    uint32_t a;
    asm("{ .reg .u64 t; cvta.to.shared.u64 t, %1; cvt.u32.u64 %0, t; }" : "=r"(a) : "l"(p));
    return a;
}
__device__ __forceinline__ void ldsm_x4(uint32_t* r, uint32_t addr) {
    asm volatile("ldmatrix.sync.aligned.m8n8.x4.shared.b16 {%0,%1,%2,%3}, [%4];"
        : "=r"(r[0]), "=r"(r[1]), "=r"(r[2]), "=r"(r[3]) : "r"(addr));
}
__device__ __forceinline__ void mma_bf16(float* d, const uint32_t* a, const uint32_t* b) {
    asm volatile("mma.sync.aligned.m16n8k16.row.col.f32.bf16.bf16.f32 "
        "{%0,%1,%2,%3}, {%4,%5,%6,%7}, {%8,%9}, {%0,%1,%2,%3};"
        : "+f"(d[0]), "+f"(d[1]), "+f"(d[2]), "+f"(d[3])
        : "r"(a[0]), "r"(a[1]), "r"(a[2]), "r"(a[3]), "r"(b[0]), "r"(b[1]));
}
__device__ __forceinline__ uint32_t pack2(__nv_bfloat16 x, __nv_bfloat16 y) {
    uint32_t lo = __bfloat16_as_ushort(x), hi = __bfloat16_as_ushort(y);
    return (hi << 16) | lo;
}
__device__ __forceinline__ void cp16(uint32_t dst, const void* src) {
    asm volatile("cp.async.cg.shared.global [%0], [%1], 16;" :: "r"(dst), "l"(src));
}
#define CP_COMMIT() asm volatile("cp.async.commit_group;" ::: "memory")
#define CP_WAIT(n)  asm volatile("cp.async.wait_group %0;" :: "n"(n) : "memory")

// ======================= pre-convert f32 -> bf16 hi/lo =======================
__global__ __launch_bounds__(256) void conv_kernel(
    const float* __restrict__ src, __nv_bfloat16* __restrict__ dh,
    __nv_bfloat16* __restrict__ dl)
{
    size_t i = ((size_t)blockIdx.x * blockDim.x + threadIdx.x) * 4;
    float4 v = *(const float4*)(src + i);
    __nv_bfloat16 hx = __float2bfloat16_rn(v.x), hy = __float2bfloat16_rn(v.y);
    __nv_bfloat16 hz = __float2bfloat16_rn(v.z), hw = __float2bfloat16_rn(v.w);
    uint2 hi = make_uint2(pack2(hx, hy), pack2(hz, hw));
    uint2 lo = make_uint2(
        pack2(__float2bfloat16_rn(v.x - __bfloat162float(hx)),
              __float2bfloat16_rn(v.y - __bfloat162float(hy))),
        pack2(__float2bfloat16_rn(v.z - __bfloat162float(hz)),
              __float2bfloat16_rn(v.w - __bfloat162float(hw))));
    *(uint2*)(dh + i) = hi;
    *(uint2*)(dl + i) = lo;
}

// ======================= bf16-split GEMM (3-stage cp.async pipeline) =======================
// C[m][n] = sum_k A[m][k]*B[n][k]; A hi/lo = g_xh/g_xl, B hi/lo = g_wh/g_wl, C = g_h
// Block tile 128x128, BK=64, 8 warps (2x4), warp tile 64x32, mma m16n8k16.
#define ROWB 144                        // padded row stride (bytes) = 72 bf16
#define TILE_B (128 * ROWB)             // 18432
#define STAGE_B (4 * TILE_B)            // 73728
#define NSTAGE 3
#define GEMM_SMEM (NSTAGE * STAGE_B)    // 221184

__global__ __launch_bounds__(256, 1) void gemm_split()
{
    extern __shared__ char smem[];
    const uint32_t sb = smem_u32(smem);
    const int tid = threadIdx.x, wid = tid >> 5, lid = tid & 31;
    const int m0 = blockIdx.y * 128, n0 = blockIdx.x * 128;
    const int warp_m = (wid >> 2) * 64, warp_n = (wid & 3) * 32;

    // fill mapping: thread t -> row t>>1, 32 bf16 (64B) at col (t&1)*32 within 64-col chunk
    const int frow = tid >> 1, fhalf = tid & 1;
    const uint32_t fbase = (uint32_t)frow * ROWB + fhalf * 64;   // byte offset within a tile
    const size_t arow = (size_t)(m0 + frow) * NF + fhalf * 32;
    const size_t brow = (size_t)(n0 + frow) * NF + fhalf * 32;

    // ldmatrix per-lane base offsets (bytes, within a tile)
    const uint32_t a_off = (uint32_t)((warp_m + (lid & 15)) * 72 + (lid >> 4) * 8) * 2;
    const uint32_t b_off = (uint32_t)((warp_n + (lid & 7) + (lid >> 4) * 8) * 72
                                      + ((lid >> 3) & 1) * 8) * 2;

    float acc[4][4][4];
    #pragma unroll
    for (int i = 0; i < 4; i++)
        #pragma unroll
        for (int j = 0; j < 4; j++)
            #pragma unroll
            for (int v = 0; v < 4; v++) acc[i][j][v] = 0.f;

    // ---- issue a fill for chunk kc into stage s ----
    auto issue = [&](int kc, int s) {
        const uint32_t dst = sb + (uint32_t)s * STAGE_B + fbase;
        const int kcol = kc * 64;
        const __nv_bfloat16* s0 = g_xh + arow + kcol;
        const __nv_bfloat16* s1 = g_xl + arow + kcol;
        const __nv_bfloat16* s2 = g_wh + brow + kcol;
        const __nv_bfloat16* s3 = g_wl + brow + kcol;
        #pragma unroll
        for (int j = 0; j < 4; j++) {
            cp16(dst + 0 * TILE_B + j * 16, s0 + j * 8);
            cp16(dst + 1 * TILE_B + j * 16, s1 + j * 8);
            cp16(dst + 2 * TILE_B + j * 16, s2 + j * 8);
            cp16(dst + 3 * TILE_B + j * 16, s3 + j * 8);
        }
        CP_COMMIT();
    };

    issue(0, 0);
    issue(1, 1);

    int stg = 0;                     // stage holding chunk kc
    #pragma unroll 1
    for (int kc = 0; kc < 8; kc++) {
        if (kc + 2 < 8) {
            int s2 = stg + 2; if (s2 >= NSTAGE) s2 -= NSTAGE;
            issue(kc + 2, s2);
            CP_WAIT(2);
        } else if (kc + 2 == 8) {
            CP_WAIT(1);
        } else {
            CP_WAIT(0);
        }
        __syncthreads();
        // ---- compute on stage stg ----
        {
            const uint32_t base = sb + (uint32_t)stg * STAGE_B;
            const uint32_t aHi = base + a_off;
            const uint32_t aLo = aHi + TILE_B;
            const uint32_t bHi = base + 2 * TILE_B + b_off;
            const uint32_t bLo = bHi + TILE_B;
            #pragma unroll
            for (int ks = 0; ks < 4; ks++) {
                uint32_t ah[4][4], al[4][4], bh[2][4], bl[2][4];
                #pragma unroll
                for (int mt = 0; mt < 4; mt++) {
                    ldsm_x4(ah[mt], aHi + mt * (16 * ROWB) + ks * 32);
                    ldsm_x4(al[mt], aLo + mt * (16 * ROWB) + ks * 32);
                }
                #pragma unroll
                for (int np = 0; np < 2; np++) {
                    ldsm_x4(bh[np], bHi + np * (16 * ROWB) + ks * 32);
                    ldsm_x4(bl[np], bLo + np * (16 * ROWB) + ks * 32);
                }
                #pragma unroll
                for (int mt = 0; mt < 4; mt++)
                    #pragma unroll
                    for (int nt = 0; nt < 4; nt++) {
                        const uint32_t* bhp = &bh[nt >> 1][(nt & 1) * 2];
                        const uint32_t* blp = &bl[nt >> 1][(nt & 1) * 2];
                        mma_bf16(acc[mt][nt], ah[mt], bhp);
                        mma_bf16(acc[mt][nt], ah[mt], blp);
                        mma_bf16(acc[mt][nt], al[mt], bhp);
                    }
            }
        }
        stg++; if (stg >= NSTAGE) stg -= NSTAGE;
    }

    // ---- epilogue: write C ----
    #pragma unroll
    for (int mt = 0; mt < 4; mt++) {
        const int row0 = m0 + warp_m + mt * 16 + (lid >> 2);
        #pragma unroll
        for (int nt = 0; nt < 4; nt++) {
            const int col = n0 + warp_n + nt * 8 + (lid & 3) * 2;
            *(float2*)(g_h + (size_t)row0 * NHD + col) =
                make_float2(acc[mt][nt][0], acc[mt][nt][1]);
            *(float2*)(g_h + (size_t)(row0 + 8) * NHD + col) =
                make_float2(acc[mt][nt][2], acc[mt][nt][3]);
        }
    }
}

// ======================= graph pipeline (unchanged, passing) =======================
__global__ void init_kernel(int N)
{
    int i = blockIdx.x * blockDim.x + threadIdx.x;
    if (i < N) { g_last[i] = -1; g_cnt[i] = 0; g_cur[i] = 0; }
}

__global__ void score_kernel(const float* __restrict__ a, int BN)
{
    int warp = (blockIdx.x * blockDim.x + threadIdx.x) >> 5;
    int lane = threadIdx.x & 31;
    if (warp >= BN) return;
    const float* hrow = g_h + (size_t)warp * NHD + lane * 16;
    int head  = lane >> 2;
    int dbase = (lane & 3) * 16;
    float p1 = 0.f, p2 = 0.f;
    #pragma unroll
    for (int i = 0; i < 16; i++) {
        float v = hrow[i];
        p1 += v * a[dbase + i];
        p2 += v * a[64 + dbase + i];
    }
    p1 += __shfl_xor_sync(0xffffffffu, p1, 1);
    p2 += __shfl_xor_sync(0xffffffffu, p2, 1);
    p1 += __shfl_xor_sync(0xffffffffu, p1, 2);
    p2 += __shfl_xor_sync(0xffffffffu, p2, 2);
    if ((lane & 3) == 0) {
        g_s1[(size_t)warp * NH + head] = p1;
        g_s2[(size_t)warp * NH + head] = p2;
    }
}

__global__ void edge1_kernel(const int* __restrict__ ei, int E)
{
    int e = blockIdx.x * blockDim.x + threadIdx.x;
    if (e >= E) return;
    int s = ei[e];
    atomicMax(&g_last[s], e);
    atomicAdd(&g_cnt[s], 1);
}

__global__ void scan_kernel()
{
    __shared__ int sums[1024];
    int tid = threadIdx.x;
    int base = tid * 8;
    int local[8];
    int s = 0;
    #pragma unroll
    for (int i = 0; i < 8; i++) { local[i] = s; s += g_cnt[base + i]; }
    sums[tid] = s;
    __syncthreads();
    for (int off = 1; off < 1024; off <<= 1) {
        int v = 0;
        if (tid >= off) v = sums[tid - off];
        __syncthreads();
        sums[tid] += v;
        __syncthreads();
    }
    int prev = (tid == 0) ? 0 : sums[tid - 1];
    #pragma unroll
    for (int i = 0; i < 8; i++) g_off[base + i] = prev + local[i];
    if (tid == 1023) g_off[NN] = sums[1023];
}

__global__ void edge2_kernel(const int* __restrict__ ei, int E)
{
    int e = blockIdx.x * blockDim.x + threadIdx.x;
    if (e >= E) return;
    int s = ei[e];
    int p = atomicAdd(&g_cur[s], 1);
    g_csr[g_off[s] + p] = ei[E + e];
}

__global__ void w_kernel(const int* __restrict__ ei, int N, int E)
{
    int idx = blockIdx.x * blockDim.x + threadIdx.x;
    if (idx >= N * NH) return;
    int n = idx >> 3, h = idx & 7;
    int le = g_last[n];
    float w0 = 0.f, w1 = 0.f;
    if (le >= 0) {
        int dle = ei[E + le];
        float sc0 = g_s1[((size_t)0 * N + n) * NH + h] + g_s2[((size_t)0 * N + dle) * NH + h];
        float sc1 = g_s1[((size_t)1 * N + n) * NH + h] + g_s2[((size_t)1 * N + dle) * NH + h];
        sc0 = sc0 > 0.f ? sc0 : 0.2f * sc0;
        sc1 = sc1 > 0.f ? sc1 : 0.2f * sc1;
        float m  = fmaxf(sc0, sc1);
        float e0 = expf(sc0 - m), e1 = expf(sc1 - m);
        float inv = 1.f / (e0 + e1);
        w0 = e0 * inv; w1 = e1 * inv;
    }
    g_w[((size_t)0 * N + n) * NH + h] = w0;
    g_w[((size_t)1 * N + n) * NH + h] = w1;
}

__global__ __launch_bounds__(128) void agg_kernel(float* __restrict__ out, int N)
{
    int bn = blockIdx.x;
    int n  = bn & (N - 1);
    int b  = bn >> 13;
    int tid = threadIdx.x;
    __shared__ float s[NHD];

    int beg = g_off[n], end = g_off[n + 1];
    const float* hbase = g_h + (size_t)b * N * NHD;
    float4 acc = make_float4(0.f, 0.f, 0.f, 0.f);
    for (int j = beg; j < end; j++) {
        int d = g_csr[j];
        const float4* row = (const float4*)(hbase + (size_t)d * NHD);
        float4 v = row[tid];
        acc.x += v.x; acc.y += v.y; acc.z += v.z; acc.w += v.w;
    }
    ((float4*)s)[tid] = acc;
    __syncthreads();
    if (tid < ND) {
        const float* wrow = g_w + (size_t)bn * NH;
        float o = 0.f;
        #pragma unroll
        for (int h = 0; h < NH; h++) o += wrow[h] * s[h * ND + tid];
        out[(size_t)bn * ND + tid] = o * 0.125f;
    }
}

extern "C" void kernel_launch(void* const* d_in, const int* in_sizes, int n_in,
                              void* d_out, int out_size)
{
    const float* x  = (const float*)d_in[0];
    const int*   ei = (const int*)d_in[1];
    const float* W  = (const float*)d_in[2];
    const float* a  = (const float*)d_in[3];
    float* out = (float*)d_out;

    const int N = NN;
    const int E = in_sizes[1] / 2;
    const int M = NM;

    cudaFuncSetAttribute(gemm_split, cudaFuncAttributeMaxDynamicSharedMemorySize, GEMM_SMEM);

    // resolve device-global scratch addresses (host side, graph-safe: no alloc)
    __nv_bfloat16 *xh, *xl, *wh, *wl;
    cudaGetSymbolAddress((void**)&xh, g_xh);
    cudaGetSymbolAddress((void**)&xl, g_xl);
    cudaGetSymbolAddress((void**)&wh, g_wh);
    cudaGetSymbolAddress((void**)&wl, g_wl);

    init_kernel<<<(N + 255) / 256, 256>>>(N);
    conv_kernel<<<(M * NF / 4) / 256, 256>>>(x, xh, xl);
    conv_kernel<<<(NHD * NF / 4) / 256, 256>>>(W, wh, wl);
    gemm_split<<<dim3(NHD / 128, M / 128), 256, GEMM_SMEM>>>();
    score_kernel<<<(M * 32 + 255) / 256, 256>>>(a, M);
    edge1_kernel<<<(E + 255) / 256, 256>>>(ei, E);
    scan_kernel<<<1, 1024>>>();
    edge2_kernel<<<(E + 255) / 256, 256>>>(ei, E);
    w_kernel<<<(N * NH + 255) / 256, 256>>>(ei, N, E);
    agg_kernel<<<NB * NN, 128>>>(out, N);
}

// round 5
// speedup vs baseline: 1.7850x; 1.0967x over previous
#include <cuda_runtime.h>
#include <cuda_bf16.h>
#include <math.h>
#include <stdint.h>

// Problem constants (fixed by the dataset)
#define NB 2
#define NN 8192
#define NF 512
#define NHD 512   // H*D
#define NH 8
#define ND 64
#define NM (NB * NN)   // 16384

// -------- scratch (device globals; no allocation allowed) --------
__device__ float g_h[NB * NN * NHD];                 // 32 MB
__device__ __nv_bfloat16 g_xh[NM * NF];              // 16 MB
__device__ __nv_bfloat16 g_xl[NM * NF];              // 16 MB
__device__ __nv_bfloat16 g_wh[NHD * NF];             // 0.5 MB
__device__ __nv_bfloat16 g_wl[NHD * NF];             // 0.5 MB
__device__ float g_s1[NB * NN * NH];
__device__ float g_s2[NB * NN * NH];
__device__ float g_w[NB * NN * NH];
__device__ int   g_last[NN];
__device__ int   g_cnt[NN];
__device__ int   g_cur[NN];
__device__ int   g_off[NN + 1];
__device__ int   g_csr[131072];

// ======================= helpers =======================
__device__ __forceinline__ uint32_t smem_u32(const void* p) {
    uint32_t a;
    asm("{ .reg .u64 t; cvta.to.shared.u64 t, %1; cvt.u32.u64 %0, t; }" : "=r"(a) : "l"(p));
    return a;
}
__device__ __forceinline__ void ldsm_x4(uint32_t* r, uint32_t addr) {
    asm volatile("ldmatrix.sync.aligned.m8n8.x4.shared.b16 {%0,%1,%2,%3}, [%4];"
        : "=r"(r[0]), "=r"(r[1]), "=r"(r[2]), "=r"(r[3]) : "r"(addr));
}
__device__ __forceinline__ void mma_bf16(float* d, const uint32_t* a, const uint32_t* b) {
    asm volatile("mma.sync.aligned.m16n8k16.row.col.f32.bf16.bf16.f32 "
        "{%0,%1,%2,%3}, {%4,%5,%6,%7}, {%8,%9}, {%0,%1,%2,%3};"
        : "+f"(d[0]), "+f"(d[1]), "+f"(d[2]), "+f"(d[3])
        : "r"(a[0]), "r"(a[1]), "r"(a[2]), "r"(a[3]), "r"(b[0]), "r"(b[1]));
}
__device__ __forceinline__ uint32_t pack2(__nv_bfloat16 x, __nv_bfloat16 y) {
    uint32_t lo = __bfloat16_as_ushort(x), hi = __bfloat16_as_ushort(y);
    return (hi << 16) | lo;
}
__device__ __forceinline__ void cp16(uint32_t dst, const void* src) {
    asm volatile("cp.async.cg.shared.global [%0], [%1], 16;" :: "r"(dst), "l"(src));
}
#define CP_COMMIT() asm volatile("cp.async.commit_group;" ::: "memory")
#define CP_WAIT(n)  asm volatile("cp.async.wait_group %0;" :: "n"(n) : "memory")

// ======================= pre-convert f32 -> bf16 hi/lo =======================
__global__ __launch_bounds__(256) void conv_kernel(
    const float* __restrict__ src, __nv_bfloat16* __restrict__ dh,
    __nv_bfloat16* __restrict__ dl)
{
    size_t i = ((size_t)blockIdx.x * blockDim.x + threadIdx.x) * 4;
    float4 v = *(const float4*)(src + i);
    __nv_bfloat16 hx = __float2bfloat16_rn(v.x), hy = __float2bfloat16_rn(v.y);
    __nv_bfloat16 hz = __float2bfloat16_rn(v.z), hw = __float2bfloat16_rn(v.w);
    uint2 hi = make_uint2(pack2(hx, hy), pack2(hz, hw));
    uint2 lo = make_uint2(
        pack2(__float2bfloat16_rn(v.x - __bfloat162float(hx)),
              __float2bfloat16_rn(v.y - __bfloat162float(hy))),
        pack2(__float2bfloat16_rn(v.z - __bfloat162float(hz)),
              __float2bfloat16_rn(v.w - __bfloat162float(hw))));
    *(uint2*)(dh + i) = hi;
    *(uint2*)(dl + i) = lo;
}

// ======================= bf16-split GEMM (BK=32, 2 stages, 2 CTAs/SM) =======================
// C[m][n] = sum_k A[m][k]*B[n][k]; A hi/lo = g_xh/g_xl, B hi/lo = g_wh/g_wl, C = g_h
// Block tile 128x128, BK=32, 8 warps (2x4), warp tile 64x32, mma m16n8k16.
#define ROWB 80                         // padded row stride (bytes) = 40 bf16 (32 data + pad)
#define TILE_B (128 * ROWB)             // 10240
#define STAGE_B (4 * TILE_B)            // 40960
#define NSTAGE 2
#define GEMM_SMEM (NSTAGE * STAGE_B)    // 81920
#define NKC (NF / 32)                   // 16 chunks

__global__ __launch_bounds__(256, 2) void gemm_split()
{
    extern __shared__ char smem[];
    const uint32_t sb = smem_u32(smem);
    const int tid = threadIdx.x, wid = tid >> 5, lid = tid & 31;
    const int m0 = blockIdx.y * 128, n0 = blockIdx.x * 128;
    const int warp_m = (wid >> 2) * 64, warp_n = (wid & 3) * 32;

    // fill mapping: thread t -> row t>>1, 16 bf16 (32B) at half (t&1)
    const int frow = tid >> 1, fhalf = tid & 1;
    const uint32_t fbase = (uint32_t)frow * ROWB + fhalf * 32;   // byte offset within a tile
    const size_t arow = (size_t)(m0 + frow) * NF + fhalf * 16;
    const size_t brow = (size_t)(n0 + frow) * NF + fhalf * 16;

    // ldmatrix per-lane base offsets (bytes, within a tile); row stride 40 bf16
    const uint32_t a_off = (uint32_t)((warp_m + (lid & 15)) * 40 + (lid >> 4) * 8) * 2;
    const uint32_t b_off = (uint32_t)((warp_n + (lid & 7) + (lid >> 4) * 8) * 40
                                      + ((lid >> 3) & 1) * 8) * 2;

    float acc[4][4][4];
    #pragma unroll
    for (int i = 0; i < 4; i++)
        #pragma unroll
        for (int j = 0; j < 4; j++)
            #pragma unroll
            for (int v = 0; v < 4; v++) acc[i][j][v] = 0.f;

    // ---- issue a fill for chunk kc into stage s ----
    auto issue = [&](int kc, int s) {
        const uint32_t dst = sb + (uint32_t)s * STAGE_B + fbase;
        const int kcol = kc * 32;
        const __nv_bfloat16* s0 = g_xh + arow + kcol;
        const __nv_bfloat16* s1 = g_xl + arow + kcol;
        const __nv_bfloat16* s2 = g_wh + brow + kcol;
        const __nv_bfloat16* s3 = g_wl + brow + kcol;
        #pragma unroll
        for (int j = 0; j < 2; j++) {
            cp16(dst + 0 * TILE_B + j * 16, s0 + j * 8);
            cp16(dst + 1 * TILE_B + j * 16, s1 + j * 8);
            cp16(dst + 2 * TILE_B + j * 16, s2 + j * 8);
            cp16(dst + 3 * TILE_B + j * 16, s3 + j * 8);
        }
        CP_COMMIT();
    };

    issue(0, 0);

    #pragma unroll 1
    for (int kc = 0; kc < NKC; kc++) {
        CP_WAIT(0);
        __syncthreads();                 // all warps done with the other stage
        if (kc + 1 < NKC) issue(kc + 1, (kc + 1) & 1);
        // ---- compute on stage kc&1 ----
        {
            const uint32_t base = sb + (uint32_t)(kc & 1) * STAGE_B;
            const uint32_t aHi = base + a_off;
            const uint32_t aLo = aHi + TILE_B;
            const uint32_t bHi = base + 2 * TILE_B + b_off;
            const uint32_t bLo = bHi + TILE_B;
            #pragma unroll
            for (int ks = 0; ks < 2; ks++) {
                uint32_t bh[2][4], bl[2][4];
                #pragma unroll
                for (int np = 0; np < 2; np++) {
                    ldsm_x4(bh[np], bHi + np * (16 * ROWB) + ks * 32);
                    ldsm_x4(bl[np], bLo + np * (16 * ROWB) + ks * 32);
                }
                #pragma unroll
                for (int mt = 0; mt < 4; mt++) {
                    uint32_t ah[4], al[4];
                    ldsm_x4(ah, aHi + mt * (16 * ROWB) + ks * 32);
                    ldsm_x4(al, aLo + mt * (16 * ROWB) + ks * 32);
                    #pragma unroll
                    for (int nt = 0; nt < 4; nt++) {
                        const uint32_t* bhp = &bh[nt >> 1][(nt & 1) * 2];
                        const uint32_t* blp = &bl[nt >> 1][(nt & 1) * 2];
                        mma_bf16(acc[mt][nt], ah, bhp);
                        mma_bf16(acc[mt][nt], ah, blp);
                        mma_bf16(acc[mt][nt], al, bhp);
                    }
                }
            }
        }
        __syncthreads();                 // done reading this stage before refill
    }

    // ---- epilogue: write C ----
    #pragma unroll
    for (int mt = 0; mt < 4; mt++) {
        const int row0 = m0 + warp_m + mt * 16 + (lid >> 2);
        #pragma unroll
        for (int nt = 0; nt < 4; nt++) {
            const int col = n0 + warp_n + nt * 8 + (lid & 3) * 2;
            *(float2*)(g_h + (size_t)row0 * NHD + col) =
                make_float2(acc[mt][nt][0], acc[mt][nt][1]);
            *(float2*)(g_h + (size_t)(row0 + 8) * NHD + col) =
                make_float2(acc[mt][nt][2], acc[mt][nt][3]);
        }
    }
}

// ======================= graph pipeline (unchanged, passing) =======================
__global__ void init_kernel(int N)
{
    int i = blockIdx.x * blockDim.x + threadIdx.x;
    if (i < N) { g_last[i] = -1; g_cnt[i] = 0; g_cur[i] = 0; }
}

__global__ void score_kernel(const float* __restrict__ a, int BN)
{
    int warp = (blockIdx.x * blockDim.x + threadIdx.x) >> 5;
    int lane = threadIdx.x & 31;
    if (warp >= BN) return;
    const float* hrow = g_h + (size_t)warp * NHD + lane * 16;
    int head  = lane >> 2;
    int dbase = (lane & 3) * 16;
    float p1 = 0.f, p2 = 0.f;
    #pragma unroll
    for (int i = 0; i < 16; i++) {
        float v = hrow[i];
        p1 += v * a[dbase + i];
        p2 += v * a[64 + dbase + i];
    }
    p1 += __shfl_xor_sync(0xffffffffu, p1, 1);
    p2 += __shfl_xor_sync(0xffffffffu, p2, 1);
    p1 += __shfl_xor_sync(0xffffffffu, p1, 2);
    p2 += __shfl_xor_sync(0xffffffffu, p2, 2);
    if ((lane & 3) == 0) {
        g_s1[(size_t)warp * NH + head] = p1;
        g_s2[(size_t)warp * NH + head] = p2;
    }
}

__global__ void edge1_kernel(const int* __restrict__ ei, int E)
{
    int e = blockIdx.x * blockDim.x + threadIdx.x;
    if (e >= E) return;
    int s = ei[e];
    atomicMax(&g_last[s], e);
    atomicAdd(&g_cnt[s], 1);
}

__global__ void scan_kernel()
{
    __shared__ int sums[1024];
    int tid = threadIdx.x;
    int base = tid * 8;
    int local[8];
    int s = 0;
    #pragma unroll
    for (int i = 0; i < 8; i++) { local[i] = s; s += g_cnt[base + i]; }
    sums[tid] = s;
    __syncthreads();
    for (int off = 1; off < 1024; off <<= 1) {
        int v = 0;
        if (tid >= off) v = sums[tid - off];
        __syncthreads();
        sums[tid] += v;
        __syncthreads();
    }
    int prev = (tid == 0) ? 0 : sums[tid - 1];
    #pragma unroll
    for (int i = 0; i < 8; i++) g_off[base + i] = prev + local[i];
    if (tid == 1023) g_off[NN] = sums[1023];
}

__global__ void edge2_kernel(const int* __restrict__ ei, int E)
{
    int e = blockIdx.x * blockDim.x + threadIdx.x;
    if (e >= E) return;
    int s = ei[e];
    int p = atomicAdd(&g_cur[s], 1);
    g_csr[g_off[s] + p] = ei[E + e];
}

__global__ void w_kernel(const int* __restrict__ ei, int N, int E)
{
    int idx = blockIdx.x * blockDim.x + threadIdx.x;
    if (idx >= N * NH) return;
    int n = idx >> 3, h = idx & 7;
    int le = g_last[n];
    float w0 = 0.f, w1 = 0.f;
    if (le >= 0) {
        int dle = ei[E + le];
        float sc0 = g_s1[((size_t)0 * N + n) * NH + h] + g_s2[((size_t)0 * N + dle) * NH + h];
        float sc1 = g_s1[((size_t)1 * N + n) * NH + h] + g_s2[((size_t)1 * N + dle) * NH + h];
        sc0 = sc0 > 0.f ? sc0 : 0.2f * sc0;
        sc1 = sc1 > 0.f ? sc1 : 0.2f * sc1;
        float m  = fmaxf(sc0, sc1);
        float e0 = expf(sc0 - m), e1 = expf(sc1 - m);
        float inv = 1.f / (e0 + e1);
        w0 = e0 * inv; w1 = e1 * inv;
    }
    g_w[((size_t)0 * N + n) * NH + h] = w0;
    g_w[((size_t)1 * N + n) * NH + h] = w1;
}

__global__ __launch_bounds__(128) void agg_kernel(float* __restrict__ out, int N)
{
    int bn = blockIdx.x;
    int n  = bn & (N - 1);
    int b  = bn >> 13;
    int tid = threadIdx.x;
    __shared__ float s[NHD];

    int beg = g_off[n], end = g_off[n + 1];
    const float* hbase = g_h + (size_t)b * N * NHD;
    float4 acc = make_float4(0.f, 0.f, 0.f, 0.f);
    for (int j = beg; j < end; j++) {
        int d = g_csr[j];
        const float4* row = (const float4*)(hbase + (size_t)d * NHD);
        float4 v = row[tid];
        acc.x += v.x; acc.y += v.y; acc.z += v.z; acc.w += v.w;
    }
    ((float4*)s)[tid] = acc;
    __syncthreads();
    if (tid < ND) {
        const float* wrow = g_w + (size_t)bn * NH;
        float o = 0.f;
        #pragma unroll
        for (int h = 0; h < NH; h++) o += wrow[h] * s[h * ND + tid];
        out[(size_t)bn * ND + tid] = o * 0.125f;
    }
}

extern "C" void kernel_launch(void* const* d_in, const int* in_sizes, int n_in,
                              void* d_out, int out_size)
{
    const float* x  = (const float*)d_in[0];
    const int*   ei = (const int*)d_in[1];
    const float* W  = (const float*)d_in[2];
    const float* a  = (const float*)d_in[3];
    float* out = (float*)d_out;

    const int N = NN;
    const int E = in_sizes[1] / 2;
    const int M = NM;

    cudaFuncSetAttribute(gemm_split, cudaFuncAttributeMaxDynamicSharedMemorySize, GEMM_SMEM);

    __nv_bfloat16 *xh, *xl, *wh, *wl;
    cudaGetSymbolAddress((void**)&xh, g_xh);
    cudaGetSymbolAddress((void**)&xl, g_xl);
    cudaGetSymbolAddress((void**)&wh, g_wh);
    cudaGetSymbolAddress((void**)&wl, g_wl);

    init_kernel<<<(N + 255) / 256, 256>>>(N);
    conv_kernel<<<(M * NF / 4) / 256, 256>>>(x, xh, xl);
    conv_kernel<<<(NHD * NF / 4) / 256, 256>>>(W, wh, wl);
    gemm_split<<<dim3(NHD / 128, M / 128), 256, GEMM_SMEM>>>();
    score_kernel<<<(M * 32 + 255) / 256, 256>>>(a, M);
    edge1_kernel<<<(E + 255) / 256, 256>>>(ei, E);
    scan_kernel<<<1, 1024>>>();
    edge2_kernel<<<(E + 255) / 256, 256>>>(ei, E);
    w_kernel<<<(N * NH + 255) / 256, 256>>>(ei, N, E);
    agg_kernel<<<NB * NN, 128>>>(out, N);
}

// round 6
// speedup vs baseline: 1.8272x; 1.0236x over previous
#include <cuda_runtime.h>
#include <cuda_bf16.h>
#include <math.h>
#include <stdint.h>

// Problem constants (fixed by the dataset)
#define NB 2
#define NN 8192
#define NF 512
#define NHD 512   // H*D
#define NH 8
#define ND 64
#define NM (NB * NN)   // 16384

// -------- scratch (device globals; no allocation allowed) --------
__device__ float g_h[NB * NN * NHD];                 // 32 MB
__device__ __nv_bfloat16 g_xh[NM * NF];              // 16 MB
__device__ __nv_bfloat16 g_xl[NM * NF];              // 16 MB
__device__ __nv_bfloat16 g_wh[NHD * NF];             // 0.5 MB
__device__ __nv_bfloat16 g_wl[NHD * NF];             // 0.5 MB
__device__ float g_s1[NB * NN * NH];
__device__ float g_s2[NB * NN * NH];
__device__ float g_w[NB * NN * NH];
__device__ int   g_last[NN];
__device__ int   g_cnt[NN];
__device__ int   g_cur[NN];
__device__ int   g_off[NN + 1];
__device__ int   g_csr[131072];

// ======================= helpers =======================
__device__ __forceinline__ uint32_t smem_u32(const void* p) {
    uint32_t a;
    asm("{ .reg .u64 t; cvta.to.shared.u64 t, %1; cvt.u32.u64 %0, t; }" : "=r"(a) : "l"(p));
    return a;
}
__device__ __forceinline__ void ldsm_x4(uint32_t* r, uint32_t addr) {
    asm volatile("ldmatrix.sync.aligned.m8n8.x4.shared.b16 {%0,%1,%2,%3}, [%4];"
        : "=r"(r[0]), "=r"(r[1]), "=r"(r[2]), "=r"(r[3]) : "r"(addr));
}
__device__ __forceinline__ void mma_bf16(float* d, const uint32_t* a, const uint32_t* b) {
    asm volatile("mma.sync.aligned.m16n8k16.row.col.f32.bf16.bf16.f32 "
        "{%0,%1,%2,%3}, {%4,%5,%6,%7}, {%8,%9}, {%0,%1,%2,%3};"
        : "+f"(d[0]), "+f"(d[1]), "+f"(d[2]), "+f"(d[3])
        : "r"(a[0]), "r"(a[1]), "r"(a[2]), "r"(a[3]), "r"(b[0]), "r"(b[1]));
}
__device__ __forceinline__ uint32_t pack2(__nv_bfloat16 x, __nv_bfloat16 y) {
    uint32_t lo = __bfloat16_as_ushort(x), hi = __bfloat16_as_ushort(y);
    return (hi << 16) | lo;
}
__device__ __forceinline__ void cp16(uint32_t dst, const void* src) {
    asm volatile("cp.async.cg.shared.global [%0], [%1], 16;" :: "r"(dst), "l"(src));
}
#define CP_COMMIT() asm volatile("cp.async.commit_group;" ::: "memory")
#define CP_WAIT(n)  asm volatile("cp.async.wait_group %0;" :: "n"(n) : "memory")

// ======================= pre-convert f32 -> bf16 hi/lo =======================
__global__ __launch_bounds__(256) void conv_kernel(
    const float* __restrict__ src, __nv_bfloat16* __restrict__ dh,
    __nv_bfloat16* __restrict__ dl)
{
    size_t i = ((size_t)blockIdx.x * blockDim.x + threadIdx.x) * 4;
    float4 v = *(const float4*)(src + i);
    __nv_bfloat16 hx = __float2bfloat16_rn(v.x), hy = __float2bfloat16_rn(v.y);
    __nv_bfloat16 hz = __float2bfloat16_rn(v.z), hw = __float2bfloat16_rn(v.w);
    uint2 hi = make_uint2(pack2(hx, hy), pack2(hz, hw));
    uint2 lo = make_uint2(
        pack2(__float2bfloat16_rn(v.x - __bfloat162float(hx)),
              __float2bfloat16_rn(v.y - __bfloat162float(hy))),
        pack2(__float2bfloat16_rn(v.z - __bfloat162float(hz)),
              __float2bfloat16_rn(v.w - __bfloat162float(hw))));
    *(uint2*)(dh + i) = hi;
    *(uint2*)(dl + i) = lo;
}

// ======================= bf16-split GEMM (BK=32, 3 stages, swizzled, 2 CTAs/SM) =======================
// Tile layout: 128 logical rows x 64B (32 bf16), packed as 64 physical rows x 128B.
// Logical (lr, 16B-unit c) -> phys addr = (lr>>1)*128 + (((lr&1)*4 + c) ^ ((lr>>1)&7))*16.
#define TILE_B 8192
#define STAGE_B (4 * TILE_B)            // 32768: Ah, Al, Bh, Bl
#define NSTAGE 3
#define GEMM_SMEM (NSTAGE * STAGE_B)    // 98304
#define NKC (NF / 32)                   // 16 chunks

__global__ __launch_bounds__(256, 2) void gemm_split()
{
    extern __shared__ char smem[];
    const uint32_t sb = smem_u32(smem);
    const int tid = threadIdx.x, wid = tid >> 5, lid = tid & 31;
    const int m0 = blockIdx.y * 128, n0 = blockIdx.x * 128;
    const int warp_m = (wid >> 2) * 64, warp_n = (wid & 3) * 32;

    // ---- fill constants: thread t -> logical row t>>1, 32B half (t&1) ----
    const int flr = tid >> 1, fh = tid & 1;
    const uint32_t fu0 = (uint32_t)(flr & 1) * 4 + fh * 2;
    const uint32_t fmask = ((uint32_t)flr >> 1) & 7;
    const uint32_t d0 = ((uint32_t)(flr >> 1)) * 128 + ((fu0 ^ fmask) << 4);
    const uint32_t d1 = ((uint32_t)(flr >> 1)) * 128 + (((fu0 + 1) ^ fmask) << 4);
    const size_t arow = (size_t)(m0 + flr) * NF + fh * 16;
    const size_t brow = (size_t)(n0 + flr) * NF + fh * 16;

    // ---- ldsm constants ----
    const int alr = warp_m + (lid & 15);
    const uint32_t a_row = ((uint32_t)(alr >> 1)) * 128;
    const uint32_t a4 = (uint32_t)(alr & 1) * 4 + (lid >> 4);
    const uint32_t amask = ((uint32_t)(alr >> 1)) & 7;
    const int blr = warp_n + (lid & 7) + (lid >> 4) * 8;
    const uint32_t b_row = ((uint32_t)(blr >> 1)) * 128;
    const uint32_t b4 = (uint32_t)(blr & 1) * 4 + ((lid >> 3) & 1);
    const uint32_t bmask = ((uint32_t)(blr >> 1)) & 7;

    float acc[4][4][4];
    #pragma unroll
    for (int i = 0; i < 4; i++)
        #pragma unroll
        for (int j = 0; j < 4; j++)
            #pragma unroll
            for (int v = 0; v < 4; v++) acc[i][j][v] = 0.f;

    auto issue = [&](int kc, int s) {
        const uint32_t base = sb + (uint32_t)s * STAGE_B;
        const int kcol = kc * 32;
        const __nv_bfloat16* s0 = g_xh + arow + kcol;
        const __nv_bfloat16* s1 = g_xl + arow + kcol;
        const __nv_bfloat16* s2 = g_wh + brow + kcol;
        const __nv_bfloat16* s3 = g_wl + brow + kcol;
        cp16(base + 0 * TILE_B + d0, s0);     cp16(base + 0 * TILE_B + d1, s0 + 8);
        cp16(base + 1 * TILE_B + d0, s1);     cp16(base + 1 * TILE_B + d1, s1 + 8);
        cp16(base + 2 * TILE_B + d0, s2);     cp16(base + 2 * TILE_B + d1, s2 + 8);
        cp16(base + 3 * TILE_B + d0, s3);     cp16(base + 3 * TILE_B + d1, s3 + 8);
        CP_COMMIT();
    };

    issue(0, 0);
    issue(1, 1);

    int stg = 0;
    #pragma unroll 1
    for (int kc = 0; kc < NKC; kc++) {
        if (kc + 2 < NKC) { CP_WAIT(1); } else { CP_WAIT(0); }
        __syncthreads();     // also proves stage (kc+2)%3 fully consumed (computed at kc-1)
        if (kc + 2 < NKC) {
            int s2 = stg + 2; if (s2 >= NSTAGE) s2 -= NSTAGE;
            issue(kc + 2, s2);
        }
        // ---- compute on stage stg ----
        {
            const uint32_t base = sb + (uint32_t)stg * STAGE_B;
            const uint32_t aH = base + a_row;
            const uint32_t bH = base + 2 * TILE_B + b_row;
            #pragma unroll
            for (int ks = 0; ks < 2; ks++) {
                const uint32_t axo = ((a4 + 2 * ks) ^ amask) << 4;
                const uint32_t bxo = ((b4 + 2 * ks) ^ bmask) << 4;
                uint32_t bh[2][4], bl[2][4];
                #pragma unroll
                for (int np = 0; np < 2; np++) {
                    ldsm_x4(bh[np], bH + np * 1024 + bxo);
                    ldsm_x4(bl[np], bH + TILE_B + np * 1024 + bxo);
                }
                #pragma unroll
                for (int mt = 0; mt < 4; mt++) {
                    uint32_t ah[4], al[4];
                    ldsm_x4(ah, aH + mt * 1024 + axo);
                    ldsm_x4(al, aH + TILE_B + mt * 1024 + axo);
                    #pragma unroll
                    for (int nt = 0; nt < 4; nt++) {
                        const uint32_t* bhp = &bh[nt >> 1][(nt & 1) * 2];
                        const uint32_t* blp = &bl[nt >> 1][(nt & 1) * 2];
                        mma_bf16(acc[mt][nt], ah, bhp);
                        mma_bf16(acc[mt][nt], ah, blp);
                        mma_bf16(acc[mt][nt], al, bhp);
                    }
                }
            }
        }
        stg++; if (stg >= NSTAGE) stg -= NSTAGE;
    }

    // ---- epilogue: write C ----
    #pragma unroll
    for (int mt = 0; mt < 4; mt++) {
        const int row0 = m0 + warp_m + mt * 16 + (lid >> 2);
        #pragma unroll
        for (int nt = 0; nt < 4; nt++) {
            const int col = n0 + warp_n + nt * 8 + (lid & 3) * 2;
            *(float2*)(g_h + (size_t)row0 * NHD + col) =
                make_float2(acc[mt][nt][0], acc[mt][nt][1]);
            *(float2*)(g_h + (size_t)(row0 + 8) * NHD + col) =
                make_float2(acc[mt][nt][2], acc[mt][nt][3]);
        }
    }
}

// ======================= graph pipeline (unchanged, passing) =======================
__global__ void init_kernel(int N)
{
    int i = blockIdx.x * blockDim.x + threadIdx.x;
    if (i < N) { g_last[i] = -1; g_cnt[i] = 0; g_cur[i] = 0; }
}

__global__ void score_kernel(const float* __restrict__ a, int BN)
{
    int warp = (blockIdx.x * blockDim.x + threadIdx.x) >> 5;
    int lane = threadIdx.x & 31;
    if (warp >= BN) return;
    const float* hrow = g_h + (size_t)warp * NHD + lane * 16;
    int head  = lane >> 2;
    int dbase = (lane & 3) * 16;
    float p1 = 0.f, p2 = 0.f;
    #pragma unroll
    for (int i = 0; i < 16; i++) {
        float v = hrow[i];
        p1 += v * a[dbase + i];
        p2 += v * a[64 + dbase + i];
    }
    p1 += __shfl_xor_sync(0xffffffffu, p1, 1);
    p2 += __shfl_xor_sync(0xffffffffu, p2, 1);
    p1 += __shfl_xor_sync(0xffffffffu, p1, 2);
    p2 += __shfl_xor_sync(0xffffffffu, p2, 2);
    if ((lane & 3) == 0) {
        g_s1[(size_t)warp * NH + head] = p1;
        g_s2[(size_t)warp * NH + head] = p2;
    }
}

__global__ void edge1_kernel(const int* __restrict__ ei, int E)
{
    int e = blockIdx.x * blockDim.x + threadIdx.x;
    if (e >= E) return;
    int s = ei[e];
    atomicMax(&g_last[s], e);
    atomicAdd(&g_cnt[s], 1);
}

__global__ void scan_kernel()
{
    __shared__ int sums[1024];
    int tid = threadIdx.x;
    int base = tid * 8;
    int local[8];
    int s = 0;
    #pragma unroll
    for (int i = 0; i < 8; i++) { local[i] = s; s += g_cnt[base + i]; }
    sums[tid] = s;
    __syncthreads();
    for (int off = 1; off < 1024; off <<= 1) {
        int v = 0;
        if (tid >= off) v = sums[tid - off];
        __syncthreads();
        sums[tid] += v;
        __syncthreads();
    }
    int prev = (tid == 0) ? 0 : sums[tid - 1];
    #pragma unroll
    for (int i = 0; i < 8; i++) g_off[base + i] = prev + local[i];
    if (tid == 1023) g_off[NN] = sums[1023];
}

__global__ void edge2_kernel(const int* __restrict__ ei, int E)
{
    int e = blockIdx.x * blockDim.x + threadIdx.x;
    if (e >= E) return;
    int s = ei[e];
    int p = atomicAdd(&g_cur[s], 1);
    g_csr[g_off[s] + p] = ei[E + e];
}

__global__ void w_kernel(const int* __restrict__ ei, int N, int E)
{
    int idx = blockIdx.x * blockDim.x + threadIdx.x;
    if (idx >= N * NH) return;
    int n = idx >> 3, h = idx & 7;
    int le = g_last[n];
    float w0 = 0.f, w1 = 0.f;
    if (le >= 0) {
        int dle = ei[E + le];
        float sc0 = g_s1[((size_t)0 * N + n) * NH + h] + g_s2[((size_t)0 * N + dle) * NH + h];
        float sc1 = g_s1[((size_t)1 * N + n) * NH + h] + g_s2[((size_t)1 * N + dle) * NH + h];
        sc0 = sc0 > 0.f ? sc0 : 0.2f * sc0;
        sc1 = sc1 > 0.f ? sc1 : 0.2f * sc1;
        float m  = fmaxf(sc0, sc1);
        float e0 = expf(sc0 - m), e1 = expf(sc1 - m);
        float inv = 1.f / (e0 + e1);
        w0 = e0 * inv; w1 = e1 * inv;
    }
    g_w[((size_t)0 * N + n) * NH + h] = w0;
    g_w[((size_t)1 * N + n) * NH + h] = w1;
}

__global__ __launch_bounds__(128) void agg_kernel(float* __restrict__ out, int N)
{
    int bn = blockIdx.x;
    int n  = bn & (N - 1);
    int b  = bn >> 13;
    int tid = threadIdx.x;
    __shared__ float s[NHD];

    int beg = g_off[n], end = g_off[n + 1];
    const float* hbase = g_h + (size_t)b * N * NHD;
    float4 acc = make_float4(0.f, 0.f, 0.f, 0.f);
    for (int j = beg; j < end; j++) {
        int d = g_csr[j];
        const float4* row = (const float4*)(hbase + (size_t)d * NHD);
        float4 v = row[tid];
        acc.x += v.x; acc.y += v.y; acc.z += v.z; acc.w += v.w;
    }
    ((float4*)s)[tid] = acc;
    __syncthreads();
    if (tid < ND) {
        const float* wrow = g_w + (size_t)bn * NH;
        float o = 0.f;
        #pragma unroll
        for (int h = 0; h < NH; h++) o += wrow[h] * s[h * ND + tid];
        out[(size_t)bn * ND + tid] = o * 0.125f;
    }
}

extern "C" void kernel_launch(void* const* d_in, const int* in_sizes, int n_in,
                              void* d_out, int out_size)
{
    const float* x  = (const float*)d_in[0];
    const int*   ei = (const int*)d_in[1];
    const float* W  = (const float*)d_in[2];
    const float* a  = (const float*)d_in[3];
    float* out = (float*)d_out;

    const int N = NN;
    const int E = in_sizes[1] / 2;
    const int M = NM;

    cudaFuncSetAttribute(gemm_split, cudaFuncAttributeMaxDynamicSharedMemorySize, GEMM_SMEM);

    __nv_bfloat16 *xh, *xl, *wh, *wl;
    cudaGetSymbolAddress((void**)&xh, g_xh);
    cudaGetSymbolAddress((void**)&xl, g_xl);
    cudaGetSymbolAddress((void**)&wh, g_wh);
    cudaGetSymbolAddress((void**)&wl, g_wl);

    init_kernel<<<(N + 255) / 256, 256>>>(N);
    conv_kernel<<<(M * NF / 4) / 256, 256>>>(x, xh, xl);
    conv_kernel<<<(NHD * NF / 4) / 256, 256>>>(W, wh, wl);
    gemm_split<<<dim3(NHD / 128, M / 128), 256, GEMM_SMEM>>>();
    score_kernel<<<(M * 32 + 255) / 256, 256>>>(a, M);
    edge1_kernel<<<(E + 255) / 256, 256>>>(ei, E);
    scan_kernel<<<1, 1024>>>();
    edge2_kernel<<<(E + 255) / 256, 256>>>(ei, E);
    w_kernel<<<(N * NH + 255) / 256, 256>>>(ei, N, E);
    agg_kernel<<<NB * NN, 128>>>(out, N);
}

// round 7
// speedup vs baseline: 2.1010x; 1.1498x over previous
#include <cuda_runtime.h>
#include <cuda_bf16.h>
#include <math.h>
#include <stdint.h>

// Problem constants (fixed by the dataset)
#define NB 2
#define NN 8192
#define NF 512
#define NHD 512   // H*D
#define NH 8
#define ND 64
#define NM (NB * NN)   // 16384

// -------- scratch (device globals; no allocation allowed) --------
__device__ float g_h[NB * NN * NHD];                 // 32 MB
__device__ __nv_bfloat16 g_xh[NM * NF];              // 16 MB
__device__ __nv_bfloat16 g_xl[NM * NF];              // 16 MB
__device__ __nv_bfloat16 g_wh[NHD * NF];             // 0.5 MB
__device__ __nv_bfloat16 g_wl[NHD * NF];             // 0.5 MB
__device__ float g_s1[NB * NN * NH];
__device__ float g_s2[NB * NN * NH];
__device__ float g_w[NB * NN * NH];
__device__ int   g_last[NN];
__device__ int   g_cnt[NN];
__device__ int   g_cur[NN];
__device__ int   g_off[NN + 1];
__device__ int   g_csr[131072];

// ======================= helpers =======================
__device__ __forceinline__ uint32_t smem_u32(const void* p) {
    uint32_t a;
    asm("{ .reg .u64 t; cvta.to.shared.u64 t, %1; cvt.u32.u64 %0, t; }" : "=r"(a) : "l"(p));
    return a;
}
__device__ __forceinline__ void ldsm_x4(uint32_t* r, uint32_t addr) {
    asm volatile("ldmatrix.sync.aligned.m8n8.x4.shared.b16 {%0,%1,%2,%3}, [%4];"
        : "=r"(r[0]), "=r"(r[1]), "=r"(r[2]), "=r"(r[3]) : "r"(addr));
}
__device__ __forceinline__ void mma_bf16(float* d, const uint32_t* a, const uint32_t* b) {
    asm volatile("mma.sync.aligned.m16n8k16.row.col.f32.bf16.bf16.f32 "
        "{%0,%1,%2,%3}, {%4,%5,%6,%7}, {%8,%9}, {%0,%1,%2,%3};"
        : "+f"(d[0]), "+f"(d[1]), "+f"(d[2]), "+f"(d[3])
        : "r"(a[0]), "r"(a[1]), "r"(a[2]), "r"(a[3]), "r"(b[0]), "r"(b[1]));
}
__device__ __forceinline__ uint32_t pack2(__nv_bfloat16 x, __nv_bfloat16 y) {
    uint32_t lo = __bfloat16_as_ushort(x), hi = __bfloat16_as_ushort(y);
    return (hi << 16) | lo;
}
__device__ __forceinline__ void cp16(uint32_t dst, const void* src) {
    asm volatile("cp.async.cg.shared.global [%0], [%1], 16;" :: "r"(dst), "l"(src));
}
#define CP_COMMIT() asm volatile("cp.async.commit_group;" ::: "memory")
#define CP_WAIT(n)  asm volatile("cp.async.wait_group %0;" :: "n"(n) : "memory")

// ======================= pre-convert f32 -> bf16 hi/lo =======================
__global__ __launch_bounds__(256) void conv_kernel(
    const float* __restrict__ src, __nv_bfloat16* __restrict__ dh,
    __nv_bfloat16* __restrict__ dl)
{
    size_t i = ((size_t)blockIdx.x * blockDim.x + threadIdx.x) * 4;
    float4 v = *(const float4*)(src + i);
    __nv_bfloat16 hx = __float2bfloat16_rn(v.x), hy = __float2bfloat16_rn(v.y);
    __nv_bfloat16 hz = __float2bfloat16_rn(v.z), hw = __float2bfloat16_rn(v.w);
    uint2 hi = make_uint2(pack2(hx, hy), pack2(hz, hw));
    uint2 lo = make_uint2(
        pack2(__float2bfloat16_rn(v.x - __bfloat162float(hx)),
              __float2bfloat16_rn(v.y - __bfloat162float(hy))),
        pack2(__float2bfloat16_rn(v.z - __bfloat162float(hz)),
              __float2bfloat16_rn(v.w - __bfloat162float(hw))));
    *(uint2*)(dh + i) = hi;
    *(uint2*)(dl + i) = lo;
}

// ======================= bf16-split GEMM + fused score epilogue =======================
// Tile layout: 128 logical rows x 64B (32 bf16), packed as 64 physical rows x 128B.
// Logical (lr, 16B-unit c) -> phys addr = (lr>>1)*128 + (((lr&1)*4 + c) ^ ((lr>>1)&7))*16.
#define TILE_B 8192
#define STAGE_B (4 * TILE_B)            // 32768: Ah, Al, Bh, Bl
#define NSTAGE 3
#define GEMM_SMEM (NSTAGE * STAGE_B)    // 98304
#define NKC (NF / 32)                   // 16 chunks

__global__ __launch_bounds__(256, 2) void gemm_split(const float* __restrict__ ga)
{
    extern __shared__ char smem[];
    const uint32_t sb = smem_u32(smem);
    const int tid = threadIdx.x, wid = tid >> 5, lid = tid & 31;
    const int m0 = blockIdx.y * 128, n0 = blockIdx.x * 128;
    const int warp_m = (wid >> 2) * 64, warp_n = (wid & 3) * 32;

    // ---- fill constants: thread t -> logical row t>>1, 32B half (t&1) ----
    const int flr = tid >> 1, fh = tid & 1;
    const uint32_t fu0 = (uint32_t)(flr & 1) * 4 + fh * 2;
    const uint32_t fmask = ((uint32_t)flr >> 1) & 7;
    const uint32_t d0 = ((uint32_t)(flr >> 1)) * 128 + ((fu0 ^ fmask) << 4);
    const uint32_t d1 = ((uint32_t)(flr >> 1)) * 128 + (((fu0 + 1) ^ fmask) << 4);
    const size_t arow = (size_t)(m0 + flr) * NF + fh * 16;
    const size_t brow = (size_t)(n0 + flr) * NF + fh * 16;

    // ---- ldsm constants ----
    const int alr = warp_m + (lid & 15);
    const uint32_t a_row = ((uint32_t)(alr >> 1)) * 128;
    const uint32_t a4 = (uint32_t)(alr & 1) * 4 + (lid >> 4);
    const uint32_t amask = ((uint32_t)(alr >> 1)) & 7;
    const int blr = warp_n + (lid & 7) + (lid >> 4) * 8;
    const uint32_t b_row = ((uint32_t)(blr >> 1)) * 128;
    const uint32_t b4 = (uint32_t)(blr & 1) * 4 + ((lid >> 3) & 1);
    const uint32_t bmask = ((uint32_t)(blr >> 1)) & 7;

    float acc[4][4][4];
    #pragma unroll
    for (int i = 0; i < 4; i++)
        #pragma unroll
        for (int j = 0; j < 4; j++)
            #pragma unroll
            for (int v = 0; v < 4; v++) acc[i][j][v] = 0.f;

    auto issue = [&](int kc, int s) {
        const uint32_t base = sb + (uint32_t)s * STAGE_B;
        const int kcol = kc * 32;
        const __nv_bfloat16* s0 = g_xh + arow + kcol;
        const __nv_bfloat16* s1 = g_xl + arow + kcol;
        const __nv_bfloat16* s2 = g_wh + brow + kcol;
        const __nv_bfloat16* s3 = g_wl + brow + kcol;
        cp16(base + 0 * TILE_B + d0, s0);     cp16(base + 0 * TILE_B + d1, s0 + 8);
        cp16(base + 1 * TILE_B + d0, s1);     cp16(base + 1 * TILE_B + d1, s1 + 8);
        cp16(base + 2 * TILE_B + d0, s2);     cp16(base + 2 * TILE_B + d1, s2 + 8);
        cp16(base + 3 * TILE_B + d0, s3);     cp16(base + 3 * TILE_B + d1, s3 + 8);
        CP_COMMIT();
    };

    issue(0, 0);
    issue(1, 1);

    int stg = 0;
    #pragma unroll 1
    for (int kc = 0; kc < NKC; kc++) {
        if (kc + 2 < NKC) { CP_WAIT(1); } else { CP_WAIT(0); }
        __syncthreads();
        if (kc + 2 < NKC) {
            int s2 = stg + 2; if (s2 >= NSTAGE) s2 -= NSTAGE;
            issue(kc + 2, s2);
        }
        {
            const uint32_t base = sb + (uint32_t)stg * STAGE_B;
            const uint32_t aH = base + a_row;
            const uint32_t bH = base + 2 * TILE_B + b_row;
            #pragma unroll
            for (int ks = 0; ks < 2; ks++) {
                const uint32_t axo = ((a4 + 2 * ks) ^ amask) << 4;
                const uint32_t bxo = ((b4 + 2 * ks) ^ bmask) << 4;
                uint32_t bh[2][4], bl[2][4];
                #pragma unroll
                for (int np = 0; np < 2; np++) {
                    ldsm_x4(bh[np], bH + np * 1024 + bxo);
                    ldsm_x4(bl[np], bH + TILE_B + np * 1024 + bxo);
                }
                #pragma unroll
                for (int mt = 0; mt < 4; mt++) {
                    uint32_t ah[4], al[4];
                    ldsm_x4(ah, aH + mt * 1024 + axo);
                    ldsm_x4(al, aH + TILE_B + mt * 1024 + axo);
                    #pragma unroll
                    for (int nt = 0; nt < 4; nt++) {
                        const uint32_t* bhp = &bh[nt >> 1][(nt & 1) * 2];
                        const uint32_t* blp = &bl[nt >> 1][(nt & 1) * 2];
                        mma_bf16(acc[mt][nt], ah, bhp);
                        mma_bf16(acc[mt][nt], ah, blp);
                        mma_bf16(acc[mt][nt], al, bhp);
                    }
                }
            }
        }
        stg++; if (stg >= NSTAGE) stg -= NSTAGE;
    }

    // ---- epilogue 1: write C ----
    #pragma unroll
    for (int mt = 0; mt < 4; mt++) {
        const int row0 = m0 + warp_m + mt * 16 + (lid >> 2);
        #pragma unroll
        for (int nt = 0; nt < 4; nt++) {
            const int col = n0 + warp_n + nt * 8 + (lid & 3) * 2;
            *(float2*)(g_h + (size_t)row0 * NHD + col) =
                make_float2(acc[mt][nt][0], acc[mt][nt][1]);
            *(float2*)(g_h + (size_t)(row0 + 8) * NHD + col) =
                make_float2(acc[mt][nt][2], acc[mt][nt][3]);
        }
    }

    // ---- epilogue 2: fused scores s1 = h.a1, s2 = h.a2 for this tile ----
    // Block covers 2 complete heads (128 cols). sbuf[row(128)][head(2)][s1/s2].
    __syncthreads();                      // everyone done with stage smem
    float* sbuf = (float*)smem;           // 512 floats
    #pragma unroll
    for (int i = tid; i < 512; i += 256) sbuf[i] = 0.f;
    __syncthreads();

    const int hl = warp_n >> 6;           // head-local 0/1
    const int cb = (warp_n & 32);         // col base within head
    float a1v[4][2], a2v[4][2];
    #pragma unroll
    for (int nt = 0; nt < 4; nt++)
        #pragma unroll
        for (int u = 0; u < 2; u++) {
            int ch = cb + nt * 8 + (lid & 3) * 2 + u;
            a1v[nt][u] = ga[ch];
            a2v[nt][u] = ga[64 + ch];
        }
    #pragma unroll
    for (int mt = 0; mt < 4; mt++) {
        float p1a = 0.f, p1b = 0.f, p2a = 0.f, p2b = 0.f;
        #pragma unroll
        for (int nt = 0; nt < 4; nt++) {
            p1a += acc[mt][nt][0] * a1v[nt][0] + acc[mt][nt][1] * a1v[nt][1];
            p1b += acc[mt][nt][2] * a1v[nt][0] + acc[mt][nt][3] * a1v[nt][1];
            p2a += acc[mt][nt][0] * a2v[nt][0] + acc[mt][nt][1] * a2v[nt][1];
            p2b += acc[mt][nt][2] * a2v[nt][0] + acc[mt][nt][3] * a2v[nt][1];
        }
        #pragma unroll
        for (int sh = 1; sh <= 2; sh <<= 1) {
            p1a += __shfl_xor_sync(0xffffffffu, p1a, sh);
            p1b += __shfl_xor_sync(0xffffffffu, p1b, sh);
            p2a += __shfl_xor_sync(0xffffffffu, p2a, sh);
            p2b += __shfl_xor_sync(0xffffffffu, p2b, sh);
        }
        if ((lid & 3) == 0) {
            int r0 = warp_m + mt * 16 + (lid >> 2);
            atomicAdd(&sbuf[(r0 * 2 + hl) * 2 + 0], p1a);
            atomicAdd(&sbuf[(r0 * 2 + hl) * 2 + 1], p2a);
            atomicAdd(&sbuf[((r0 + 8) * 2 + hl) * 2 + 0], p1b);
            atomicAdd(&sbuf[((r0 + 8) * 2 + hl) * 2 + 1], p2b);
        }
    }
    __syncthreads();
    {
        int row = tid >> 1, hd = tid & 1;
        int hg = (n0 >> 6) + hd;          // global head
        size_t mr = (size_t)(m0 + row);
        g_s1[mr * NH + hg] = sbuf[(row * 2 + hd) * 2 + 0];
        g_s2[mr * NH + hg] = sbuf[(row * 2 + hd) * 2 + 1];
    }
}

// ======================= graph pipeline =======================
__global__ void init_kernel(int N)
{
    int i = blockIdx.x * blockDim.x + threadIdx.x;
    if (i < N) { g_last[i] = -1; g_cnt[i] = 0; g_cur[i] = 0; }
}

__global__ void edge1_kernel(const int* __restrict__ ei, int E)
{
    int e = blockIdx.x * blockDim.x + threadIdx.x;
    if (e >= E) return;
    int s = ei[e];
    atomicMax(&g_last[s], e);
    atomicAdd(&g_cnt[s], 1);
}

__global__ void scan_kernel()
{
    __shared__ int sums[1024];
    int tid = threadIdx.x;
    int base = tid * 8;
    int local[8];
    int s = 0;
    #pragma unroll
    for (int i = 0; i < 8; i++) { local[i] = s; s += g_cnt[base + i]; }
    sums[tid] = s;
    __syncthreads();
    for (int off = 1; off < 1024; off <<= 1) {
        int v = 0;
        if (tid >= off) v = sums[tid - off];
        __syncthreads();
        sums[tid] += v;
        __syncthreads();
    }
    int prev = (tid == 0) ? 0 : sums[tid - 1];
    #pragma unroll
    for (int i = 0; i < 8; i++) g_off[base + i] = prev + local[i];
    if (tid == 1023) g_off[NN] = sums[1023];
}

__global__ void edge2_kernel(const int* __restrict__ ei, int E)
{
    int e = blockIdx.x * blockDim.x + threadIdx.x;
    if (e >= E) return;
    int s = ei[e];
    int p = atomicAdd(&g_cur[s], 1);
    g_csr[g_off[s] + p] = ei[E + e];
}

__global__ void w_kernel(const int* __restrict__ ei, int N, int E)
{
    int idx = blockIdx.x * blockDim.x + threadIdx.x;
    if (idx >= N * NH) return;
    int n = idx >> 3, h = idx & 7;
    int le = g_last[n];
    float w0 = 0.f, w1 = 0.f;
    if (le >= 0) {
        int dle = ei[E + le];
        float sc0 = g_s1[((size_t)0 * N + n) * NH + h] + g_s2[((size_t)0 * N + dle) * NH + h];
        float sc1 = g_s1[((size_t)1 * N + n) * NH + h] + g_s2[((size_t)1 * N + dle) * NH + h];
        sc0 = sc0 > 0.f ? sc0 : 0.2f * sc0;
        sc1 = sc1 > 0.f ? sc1 : 0.2f * sc1;
        float m  = fmaxf(sc0, sc1);
        float e0 = expf(sc0 - m), e1 = expf(sc1 - m);
        float inv = 1.f / (e0 + e1);
        w0 = e0 * inv; w1 = e1 * inv;
    }
    g_w[((size_t)0 * N + n) * NH + h] = w0;
    g_w[((size_t)1 * N + n) * NH + h] = w1;
}

__global__ __launch_bounds__(128) void agg_kernel(float* __restrict__ out, int N)
{
    int bn = blockIdx.x;
    int n  = bn & (N - 1);
    int b  = bn >> 13;
    int tid = threadIdx.x;
    __shared__ float s[NHD];

    int beg = g_off[n], end = g_off[n + 1];
    const float* hbase = g_h + (size_t)b * N * NHD;
    float4 acc = make_float4(0.f, 0.f, 0.f, 0.f);
    int j = beg;
    for (; j + 1 < end; j += 2) {
        int d0 = g_csr[j], d1 = g_csr[j + 1];
        float4 v0 = ((const float4*)(hbase + (size_t)d0 * NHD))[tid];
        float4 v1 = ((const float4*)(hbase + (size_t)d1 * NHD))[tid];
        acc.x += v0.x + v1.x; acc.y += v0.y + v1.y;
        acc.z += v0.z + v1.z; acc.w += v0.w + v1.w;
    }
    if (j < end) {
        int d = g_csr[j];
        float4 v = ((const float4*)(hbase + (size_t)d * NHD))[tid];
        acc.x += v.x; acc.y += v.y; acc.z += v.z; acc.w += v.w;
    }
    ((float4*)s)[tid] = acc;
    __syncthreads();
    if (tid < ND) {
        const float* wrow = g_w + (size_t)bn * NH;
        float o = 0.f;
        #pragma unroll
        for (int h = 0; h < NH; h++) o += wrow[h] * s[h * ND + tid];
        out[(size_t)bn * ND + tid] = o * 0.125f;
    }
}

extern "C" void kernel_launch(void* const* d_in, const int* in_sizes, int n_in,
                              void* d_out, int out_size)
{
    const float* x  = (const float*)d_in[0];
    const int*   ei = (const int*)d_in[1];
    const float* W  = (const float*)d_in[2];
    const float* a  = (const float*)d_in[3];
    float* out = (float*)d_out;

    const int N = NN;
    const int E = in_sizes[1] / 2;
    const int M = NM;

    cudaFuncSetAttribute(gemm_split, cudaFuncAttributeMaxDynamicSharedMemorySize, GEMM_SMEM);

    __nv_bfloat16 *xh, *xl, *wh, *wl;
    cudaGetSymbolAddress((void**)&xh, g_xh);
    cudaGetSymbolAddress((void**)&xl, g_xl);
    cudaGetSymbolAddress((void**)&wh, g_wh);
    cudaGetSymbolAddress((void**)&wl, g_wl);

    init_kernel<<<(N + 255) / 256, 256>>>(N);
    conv_kernel<<<(M * NF / 4) / 256, 256>>>(x, xh, xl);
    conv_kernel<<<(NHD * NF / 4) / 256, 256>>>(W, wh, wl);
    edge1_kernel<<<(E + 255) / 256, 256>>>(ei, E);
    scan_kernel<<<1, 1024>>>();
    edge2_kernel<<<(E + 255) / 256, 256>>>(ei, E);
    gemm_split<<<dim3(NHD / 128, M / 128), 256, GEMM_SMEM>>>(a);
    w_kernel<<<(N * NH + 255) / 256, 256>>>(ei, N, E);
    agg_kernel<<<NB * NN, 128>>>(out, N);
}